// round 1
// baseline (speedup 1.0000x reference)
#include <cuda_runtime.h>
#include <math.h>

#define NN   8192
#define DDIM 64
#define HDIM 128
#define EDIM 256
#define CDIM 16
#define BB   4

// ---------------- scratch (device globals; no allocation allowed) ----------------
__device__ float g_r [NN];            // r[j] = rowsum(adj)^{-1/2}
__device__ float g_xt[NN * 256];      // [i][b*64+d]   = x transposed
__device__ float g_y1[NN * 256];      // conv1 pre-activation (r_i*acc + self)
__device__ float g_g1[NN * 512];      // [i][b*128+h]  = post BN layer1
__device__ float g_y2[NN * 512];      // conv2 pre-activation
__device__ float g_pt[BB * CDIM * NN];// [b*16+c][i]   = logits transposed

// ---------------- helpers ----------------
template <int NT>
__device__ __forceinline__ float block_sum(float v, float* red, int tid) {
    red[tid] = v; __syncthreads();
#pragma unroll
    for (int s = NT / 2; s > 0; s >>= 1) {
        if (tid < s) red[tid] += red[tid + s];
        __syncthreads();
    }
    float r = red[0]; __syncthreads();
    return r;
}

template <int NT>
__device__ __forceinline__ float block_max(float v, float* red, int tid) {
    red[tid] = v; __syncthreads();
#pragma unroll
    for (int s = NT / 2; s > 0; s >>= 1) {
        if (tid < s) red[tid] = fmaxf(red[tid], red[tid + s]);
        __syncthreads();
    }
    float r = red[0]; __syncthreads();
    return r;
}

// ---------------- K1: rowsum -> r ----------------
__global__ void k_rowsum(const float* __restrict__ adj, float* __restrict__ r) {
    __shared__ float red[256];
    int row = blockIdx.x;
    const float* p = adj + (size_t)row * NN;
    float s = 0.f;
    for (int c = threadIdx.x; c < NN; c += 256) s += p[c];
    float tot = block_sum<256>(s, red, threadIdx.x);
    if (threadIdx.x == 0) r[row] = (tot > 0.f) ? rsqrtf(tot) : 0.f;
}

// ---------------- K2: x[b,i,d] -> xt[i, b*64+d] ----------------
__global__ void k_xt(const float* __restrict__ x, float* __restrict__ xt) {
    int idx = blockIdx.x * 256 + threadIdx.x;   // total 4*8192*64 = 2^21
    int d = idx & 63;
    int i = (idx >> 6) & (NN - 1);
    int b = idx >> 19;
    xt[(size_t)i * 256 + b * 64 + d] = x[idx];
}

// ---------------- K3/K5: out[i,n] = r[i] * sum_j adj[j,i] * r[j] * X[j,n] + X[i,n]
// 128x128x8 tile, 256 threads, 8x8 per thread, software-prefetched gmem loads.
__global__ __launch_bounds__(256, 2)
void k_gemm(const float* __restrict__ A, const float* __restrict__ X,
            const float* __restrict__ r, float* __restrict__ out, int ncols) {
    __shared__ float As[8][128];
    __shared__ float Bs[8][128];
    const int tid   = threadIdx.x;
    const int iBase = blockIdx.y * 128;
    const int nBase = blockIdx.x * 128;
    const int lr = tid >> 5;            // 0..7  (k row within tile)
    const int lc = (tid & 31) << 2;     // 0..124 step 4
    const float* Ap = A + (size_t)lr * NN    + iBase + lc;
    const float* Xp = X + (size_t)lr * ncols + nBase + lc;
    const int ty = tid >> 4, tx = tid & 15;

    float acc[8][8];
#pragma unroll
    for (int m = 0; m < 8; m++)
#pragma unroll
        for (int n = 0; n < 8; n++) acc[m][n] = 0.f;

    float4 av = *(const float4*)Ap;
    float4 xv = *(const float4*)Xp;
    float  rj = __ldg(&r[lr]);

    for (int k0 = 0; k0 < NN; k0 += 8) {
        __syncthreads();
        *(float4*)&As[lr][lc] = av;
        float4 bv = make_float4(xv.x * rj, xv.y * rj, xv.z * rj, xv.w * rj);
        *(float4*)&Bs[lr][lc] = bv;
        __syncthreads();
        if (k0 + 8 < NN) {
            Ap += (size_t)8 * NN;
            Xp += (size_t)8 * ncols;
            av = *(const float4*)Ap;
            xv = *(const float4*)Xp;
            rj = __ldg(&r[k0 + 8 + lr]);
        }
#pragma unroll
        for (int kk = 0; kk < 8; kk++) {
            float ra[8], rb[8];
            *(float4*)&ra[0] = *(const float4*)&As[kk][ty * 8];
            *(float4*)&ra[4] = *(const float4*)&As[kk][ty * 8 + 4];
            *(float4*)&rb[0] = *(const float4*)&Bs[kk][tx * 8];
            *(float4*)&rb[4] = *(const float4*)&Bs[kk][tx * 8 + 4];
#pragma unroll
            for (int m = 0; m < 8; m++)
#pragma unroll
                for (int n = 0; n < 8; n++)
                    acc[m][n] = fmaf(ra[m], rb[n], acc[m][n]);
        }
    }

#pragma unroll
    for (int m = 0; m < 8; m++) {
        int i = iBase + ty * 8 + m;
        float ri = __ldg(&r[i]);
#pragma unroll
        for (int n = 0; n < 8; n += 4) {
            size_t off = (size_t)i * ncols + nBase + tx * 8 + n;
            float4 sv = *(const float4*)&X[off];
            float4 ov = make_float4(fmaf(ri, acc[m][n + 0], sv.x),
                                    fmaf(ri, acc[m][n + 1], sv.y),
                                    fmaf(ri, acc[m][n + 2], sv.z),
                                    fmaf(ri, acc[m][n + 3], sv.w));
            *(float4*)&out[off] = ov;
        }
    }
}

// ---------------- K4: per node: (y @ W1 + b1) -> L2norm -> relu -> BN ----------------
// block = node i, 128 threads (one per h). BN over (b,h) = 512 vals.
__global__ __launch_bounds__(128)
void k_layer1(const float* __restrict__ Y, const float* __restrict__ W1,
              const float* __restrict__ b1, float* __restrict__ G) {
    __shared__ float W1s[DDIM * HDIM];   // 32 KB
    __shared__ float Ys[BB * DDIM];
    __shared__ float red[128];
    int i = blockIdx.x, tid = threadIdx.x;
    for (int t = tid; t < DDIM * HDIM; t += 128) W1s[t] = W1[t];
    for (int t = tid; t < BB * DDIM; t += 128) Ys[t] = Y[(size_t)i * 256 + t];
    __syncthreads();

    float v[BB];
    float bias = b1[tid];
#pragma unroll
    for (int b = 0; b < BB; b++) v[b] = bias;
#pragma unroll 4
    for (int d = 0; d < DDIM; d++) {
        float w = W1s[d * HDIM + tid];
#pragma unroll
        for (int b = 0; b < BB; b++) v[b] = fmaf(Ys[b * DDIM + d], w, v[b]);
    }
    // L2 norm per (b) over h, then relu
#pragma unroll
    for (int b = 0; b < BB; b++) {
        float ss = block_sum<128>(v[b] * v[b], red, tid);
        float nrm = fmaxf(sqrtf(ss), 1e-12f);
        v[b] = fmaxf(v[b] / nrm, 0.f);
    }
    // BN over (b,h): 512 values per node
    float s = v[0] + v[1] + v[2] + v[3];
    float mean = block_sum<128>(s, red, tid) * (1.f / 512.f);
    float q = 0.f;
#pragma unroll
    for (int b = 0; b < BB; b++) { float d = v[b] - mean; q = fmaf(d, d, q); }
    float var = block_sum<128>(q, red, tid) * (1.f / 512.f);
    float inv = rsqrtf(var + 1e-5f);
#pragma unroll
    for (int b = 0; b < BB; b++)
        G[(size_t)i * 512 + b * HDIM + tid] = (v[b] - mean) * inv;
}

// ---------------- K6: per node: (y2 @ W2 + b2) -> L2norm -> relu -> BN -> @Wp+bp ----------------
// block = node i, 256 threads (one per e). BN over (b,e) = 1024 vals.
__global__ __launch_bounds__(256)
void k_layer2(const float* __restrict__ Y, const float* __restrict__ W2,
              const float* __restrict__ b2, const float* __restrict__ Wp,
              const float* __restrict__ bp, float* __restrict__ PT) {
    __shared__ float Ys[BB * HDIM];
    __shared__ float red[256];
    __shared__ float gS[BB][EDIM];
    int i = blockIdx.x, tid = threadIdx.x;
    for (int t = tid; t < BB * HDIM; t += 256) Ys[t] = Y[(size_t)i * 512 + t];
    __syncthreads();

    float v[BB];
    float bias = b2[tid];
#pragma unroll
    for (int b = 0; b < BB; b++) v[b] = bias;
#pragma unroll 4
    for (int h = 0; h < HDIM; h++) {
        float w = __ldg(&W2[h * EDIM + tid]);
#pragma unroll
        for (int b = 0; b < BB; b++) v[b] = fmaf(Ys[b * HDIM + h], w, v[b]);
    }
#pragma unroll
    for (int b = 0; b < BB; b++) {
        float ss = block_sum<256>(v[b] * v[b], red, tid);
        float nrm = fmaxf(sqrtf(ss), 1e-12f);
        v[b] = fmaxf(v[b] / nrm, 0.f);
    }
    float s = v[0] + v[1] + v[2] + v[3];
    float mean = block_sum<256>(s, red, tid) * (1.f / 1024.f);
    float q = 0.f;
#pragma unroll
    for (int b = 0; b < BB; b++) { float d = v[b] - mean; q = fmaf(d, d, q); }
    float var = block_sum<256>(q, red, tid) * (1.f / 1024.f);
    float inv = rsqrtf(var + 1e-5f);
#pragma unroll
    for (int b = 0; b < BB; b++) gS[b][tid] = (v[b] - mean) * inv;
    __syncthreads();

    // logits: 64 (b,c) pairs, each a 256-dot
    if (tid < BB * CDIM) {
        int b = tid >> 4, c = tid & 15;
        float acc = bp[c];
#pragma unroll 8
        for (int e = 0; e < EDIM; e++) acc = fmaf(gS[b][e], Wp[e * CDIM + c], acc);
        PT[(size_t)(b * CDIM + c) * NN + i] = acc;
    }
}

// ---------------- K7: softmax over nodes; write (b,i,c) layout ----------------
__global__ __launch_bounds__(256)
void k_softmax(const float* __restrict__ PT, float* __restrict__ out) {
    __shared__ float row[NN];   // 32 KB
    __shared__ float red[256];
    int bc = blockIdx.x, tid = threadIdx.x;
    int b = bc >> 4, c = bc & 15;
    const float* p = PT + (size_t)bc * NN;
    float mx = -3.4e38f;
    for (int t = tid; t < NN; t += 256) { float v = p[t]; row[t] = v; mx = fmaxf(mx, v); }
    mx = block_max<256>(mx, red, tid);
    float s = 0.f;
    for (int t = tid; t < NN; t += 256) { float e = expf(row[t] - mx); row[t] = e; s += e; }
    s = block_sum<256>(s, red, tid);
    float inv = 1.f / s;
    for (int t = tid; t < NN; t += 256)
        out[((size_t)b * NN + t) * CDIM + c] = row[t] * inv;
}

// ---------------- launch ----------------
extern "C" void kernel_launch(void* const* d_in, const int* in_sizes, int n_in,
                              void* d_out, int out_size) {
    const float* x   = (const float*)d_in[0];
    const float* adj = (const float*)d_in[1];
    const float* W1  = (const float*)d_in[2];
    const float* b1  = (const float*)d_in[3];
    const float* W2  = (const float*)d_in[4];
    const float* b2  = (const float*)d_in[5];
    const float* Wp  = (const float*)d_in[6];
    const float* bp  = (const float*)d_in[7];
    float* out = (float*)d_out;

    float *r_, *xt_, *y1_, *g1_, *y2_, *pt_;
    cudaGetSymbolAddress((void**)&r_,  g_r);
    cudaGetSymbolAddress((void**)&xt_, g_xt);
    cudaGetSymbolAddress((void**)&y1_, g_y1);
    cudaGetSymbolAddress((void**)&g1_, g_g1);
    cudaGetSymbolAddress((void**)&y2_, g_y2);
    cudaGetSymbolAddress((void**)&pt_, g_pt);

    k_rowsum<<<NN, 256>>>(adj, r_);
    k_xt<<<(BB * NN * DDIM) / 256, 256>>>(x, xt_);
    k_gemm<<<dim3(256 / 128, NN / 128), 256>>>(adj, xt_, r_, y1_, 256);
    k_layer1<<<NN, 128>>>(y1_, W1, b1, g1_);
    k_gemm<<<dim3(512 / 128, NN / 128), 256>>>(adj, g1_, r_, y2_, 512);
    k_layer2<<<NN, 256>>>(y2_, W2, b2, Wp, bp, pt_);
    k_softmax<<<BB * CDIM, 256>>>(pt_, out);
}

// round 3
// speedup vs baseline: 2.4732x; 2.4732x over previous
#include <cuda_runtime.h>
#include <cuda_bf16.h>
#include <math.h>
#include <stdint.h>

#define NN   8192
#define DDIM 64
#define HDIM 128
#define EDIM 256
#define CDIM 16
#define BB   4

// ---------------- scratch (device globals) ----------------
__device__ float g_r [NN];
__device__ float g_xt[NN * 256];        // fp32 [i][b*64+d] (residual for GEMM1)
__device__ float g_y1[NN * 256];        // conv1 output
__device__ float g_g1[NN * 512];        // post layer1 [i][b*128+h] (residual for GEMM2)
__device__ float g_y2[NN * 512];        // conv2 output
__device__ float g_pt[BB * CDIM * NN];  // logits transposed
__device__ __nv_bfloat16 g_ath[(size_t)NN * NN]; // at[i][j] = adj[j][i]*r[j], hi
__device__ __nv_bfloat16 g_atl[(size_t)NN * NN]; // lo
__device__ __nv_bfloat16 g_xbh[256 * NN];        // x^T  [n][j] hi  (B operand, K-major)
__device__ __nv_bfloat16 g_xbl[256 * NN];
__device__ __nv_bfloat16 g_g1h[512 * NN];        // g1^T [n][j] hi
__device__ __nv_bfloat16 g_g1l[512 * NN];

// ---------------- PTX helpers ----------------
__device__ __forceinline__ uint32_t smem_u32(const void* p) {
    uint32_t a;
    asm("{ .reg .u64 t; cvta.to.shared.u64 t, %1; cvt.u32.u64 %0, t; }" : "=r"(a) : "l"(p));
    return a;
}
__device__ __forceinline__ void cp16(uint32_t dst, const void* src) {
    asm volatile("cp.async.cg.shared.global [%0], [%1], 16;" :: "r"(dst), "l"(src) : "memory");
}
__device__ __forceinline__ void cp_commit() { asm volatile("cp.async.commit_group;" ::: "memory"); }
__device__ __forceinline__ void ldsm4(uint32_t& r0, uint32_t& r1, uint32_t& r2, uint32_t& r3, uint32_t a) {
    asm volatile("ldmatrix.sync.aligned.m8n8.x4.shared.b16 {%0,%1,%2,%3}, [%4];"
                 : "=r"(r0), "=r"(r1), "=r"(r2), "=r"(r3) : "r"(a));
}
__device__ __forceinline__ void mma16816(float* c, const uint32_t* a, const uint32_t* b) {
    asm volatile("mma.sync.aligned.m16n8k16.row.col.f32.bf16.bf16.f32 "
                 "{%0,%1,%2,%3}, {%4,%5,%6,%7}, {%8,%9}, {%0,%1,%2,%3};"
                 : "+f"(c[0]), "+f"(c[1]), "+f"(c[2]), "+f"(c[3])
                 : "r"(a[0]), "r"(a[1]), "r"(a[2]), "r"(a[3]), "r"(b[0]), "r"(b[1]));
}
__device__ __forceinline__ uint32_t swz(uint32_t off) { return off ^ ((off >> 3) & 0x70); }

// ---------------- small helpers ----------------
template <int NT>
__device__ __forceinline__ float block_sum(float v, float* red, int tid) {
    red[tid] = v; __syncthreads();
#pragma unroll
    for (int s = NT / 2; s > 0; s >>= 1) {
        if (tid < s) red[tid] += red[tid + s];
        __syncthreads();
    }
    float r = red[0]; __syncthreads();
    return r;
}
template <int NT>
__device__ __forceinline__ float block_max(float v, float* red, int tid) {
    red[tid] = v; __syncthreads();
#pragma unroll
    for (int s = NT / 2; s > 0; s >>= 1) {
        if (tid < s) red[tid] = fmaxf(red[tid], red[tid + s]);
        __syncthreads();
    }
    float r = red[0]; __syncthreads();
    return r;
}

// ---------------- K1: rowsum -> r ----------------
__global__ void k_rowsum(const float* __restrict__ adj, float* __restrict__ r) {
    __shared__ float red[256];
    int row = blockIdx.x;
    const float* p = adj + (size_t)row * NN;
    float s = 0.f;
    for (int c = threadIdx.x; c < NN; c += 256) s += p[c];
    float tot = block_sum<256>(s, red, threadIdx.x);
    if (threadIdx.x == 0) r[row] = (tot > 0.f) ? rsqrtf(tot) : 0.f;
}

// ---------------- K2: x -> xt (fp32, [i][n]) and x^T hi/lo ([n][j] bf16) ------
__global__ void k_prep_x(const float* __restrict__ x, float* __restrict__ xt,
                         __nv_bfloat16* __restrict__ xbh, __nv_bfloat16* __restrict__ xbl) {
    __shared__ float t[32][33];
    int i0 = blockIdx.x * 32, n0 = blockIdx.y * 32;
    int b = n0 >> 6, d0 = n0 & 63;
    int tx = threadIdx.x, ty = threadIdx.y;
#pragma unroll
    for (int dy = 0; dy < 4; dy++) {
        int rl = ty + dy * 8;
        float v = x[((size_t)b * NN + i0 + rl) * 64 + d0 + tx];
        t[rl][tx] = v;
        xt[(size_t)(i0 + rl) * 256 + n0 + tx] = v;
    }
    __syncthreads();
#pragma unroll
    for (int dy = 0; dy < 4; dy++) {
        int nl = ty + dy * 8;
        float v = t[tx][nl];
        __nv_bfloat16 h = __float2bfloat16(v);
        __nv_bfloat16 l = __float2bfloat16(v - __bfloat162float(h));
        xbh[(size_t)(n0 + nl) * NN + i0 + tx] = h;
        xbl[(size_t)(n0 + nl) * NN + i0 + tx] = l;
    }
}

// ---------------- K3: adj -> at hi/lo  (at[i][j] = adj[j][i]*r[j]) ----------------
__global__ void k_prep_adj(const float* __restrict__ adj, const float* __restrict__ r,
                           __nv_bfloat16* __restrict__ ath, __nv_bfloat16* __restrict__ atl) {
    __shared__ float t[32][33];
    int i0 = blockIdx.x * 32, j0 = blockIdx.y * 32;
    int tx = threadIdx.x, ty = threadIdx.y;
#pragma unroll
    for (int dy = 0; dy < 4; dy++) {
        int jl = ty + dy * 8;
        t[jl][tx] = adj[(size_t)(j0 + jl) * NN + i0 + tx] * __ldg(&r[j0 + jl]);
    }
    __syncthreads();
#pragma unroll
    for (int dy = 0; dy < 4; dy++) {
        int il = ty + dy * 8;
        float v = t[tx][il];
        __nv_bfloat16 h = __float2bfloat16(v);
        __nv_bfloat16 l = __float2bfloat16(v - __bfloat162float(h));
        ath[(size_t)(i0 + il) * NN + j0 + tx] = h;
        atl[(size_t)(i0 + il) * NN + j0 + tx] = l;
    }
}

// ---------------- K6b: g1 -> g1^T hi/lo ----------------
__global__ void k_g1t(const float* __restrict__ g, __nv_bfloat16* __restrict__ gh,
                      __nv_bfloat16* __restrict__ gl) {
    __shared__ float t[32][33];
    int i0 = blockIdx.x * 32, n0 = blockIdx.y * 32;
    int tx = threadIdx.x, ty = threadIdx.y;
#pragma unroll
    for (int dy = 0; dy < 4; dy++) {
        int rl = ty + dy * 8;
        t[rl][tx] = g[(size_t)(i0 + rl) * 512 + n0 + tx];
    }
    __syncthreads();
#pragma unroll
    for (int dy = 0; dy < 4; dy++) {
        int nl = ty + dy * 8;
        float v = t[tx][nl];
        __nv_bfloat16 h = __float2bfloat16(v);
        __nv_bfloat16 l = __float2bfloat16(v - __bfloat162float(h));
        gh[(size_t)(n0 + nl) * NN + i0 + tx] = h;
        gl[(size_t)(n0 + nl) * NN + i0 + tx] = l;
    }
}

// ---------------- HMMA GEMM ----------------
// Out[i, n] = r[i] * sum_j at[i][j]*Bt[n][j]  + Xres[i,n]
// A = at hi/lo [i][j] K-major ; B = Bt hi/lo [n][j] K-major.
// CTA tile 128(M) x 128(N), K-chunk 64, 3-stage cp.async, 8 warps (32x64 each),
// bf16 hi/lo split: acc += Ah*Bh + Ah*Bl + Al*Bh.
#define KCH    64
#define NCH    (NN / KCH)       // 128
#define STGB   65536            // Ah 16K | Al 16K | Bh 16K | Bl 16K
#define NSTG   3
#define GSMEM  (NSTG * STGB)

__global__ __launch_bounds__(256, 1)
void k_gemm_mma(const __nv_bfloat16* __restrict__ Ah, const __nv_bfloat16* __restrict__ Al,
                const __nv_bfloat16* __restrict__ Bh, const __nv_bfloat16* __restrict__ Bl,
                const float* __restrict__ r, const float* __restrict__ Xres,
                float* __restrict__ Out, int ncols) {
    extern __shared__ char dsm[];
    const uint32_t sb = smem_u32(dsm);
    const int tid = threadIdx.x;
    const int wid = tid >> 5, lid = tid & 31;
    const int wm = wid & 3, wn = wid >> 2;           // warp tile: rows wm*32, cols wn*64
    const int iBase = blockIdx.y * 128;
    const int nBase = blockIdx.x * 128;

    const char* bAh = (const char*)(Ah + (size_t)iBase * NN);
    const char* bAl = (const char*)(Al + (size_t)iBase * NN);
    const char* bBh = (const char*)(Bh + (size_t)nBase * NN);
    const char* bBl = (const char*)(Bl + (size_t)nBase * NN);

    // per-thread load slots: 1024 segments (128 rows x 8 segs) per matrix, 4 per thread
    int l_row[4], l_seg[4]; uint32_t l_so[4];
#pragma unroll
    for (int it = 0; it < 4; it++) {
        int idx = it * 256 + tid;
        l_row[it] = idx >> 3; l_seg[it] = idx & 7;
        l_so[it] = (uint32_t)(l_row[it] * 128) + (uint32_t)(((l_seg[it] ^ (l_row[it] & 7)) << 4));
    }

    auto load_stage = [&](int s, int c) {
        uint32_t st = sb + s * STGB;
        size_t koff = (size_t)c * 128;   // bytes: c*64 elems * 2
#pragma unroll
        for (int it = 0; it < 4; it++) {
            size_t go = (size_t)l_row[it] * (NN * 2) + koff + l_seg[it] * 16;
            cp16(st +         l_so[it], bAh + go);
            cp16(st + 16384 + l_so[it], bAl + go);
            cp16(st + 32768 + l_so[it], bBh + go);
            cp16(st + 49152 + l_so[it], bBl + go);
        }
        cp_commit();
    };

    float acc[2][8][4];
#pragma unroll
    for (int mf = 0; mf < 2; mf++)
#pragma unroll
        for (int nb = 0; nb < 8; nb++)
#pragma unroll
            for (int q = 0; q < 4; q++) acc[mf][nb][q] = 0.f;

    // precomputed lane rows (seg added per-k16)
    const int aRow = (lid & 7) + ((lid >> 3) & 1) * 8;     // + mf*16 + wm*32
    const int aSegAdd = (lid >> 4);                        // 0/1 -> k half
    const int bRowIn = (lid & 7) + ((lid >> 4) & 1) * 8;   // + p*16 + wn*64
    const int bSegAdd = (lid >> 3) & 1;

    load_stage(0, 0);
    load_stage(1, 1);

    for (int c = 0; c < NCH; c++) {
        if (c + 2 < NCH) {
            load_stage((c + 2) % NSTG, c + 2);
            asm volatile("cp.async.wait_group 2;" ::: "memory");
        } else if (c + 1 < NCH) {
            asm volatile("cp.async.wait_group 1;" ::: "memory");
        } else {
            asm volatile("cp.async.wait_group 0;" ::: "memory");
        }
        __syncthreads();

        uint32_t st = sb + (c % NSTG) * STGB;
        uint32_t sAh = st, sAl = st + 16384, sBh = st + 32768, sBl = st + 49152;
#pragma unroll
        for (int t = 0; t < 4; t++) {
            uint32_t ah[2][4], al[2][4], bh[8][2], bl[8][2];
#pragma unroll
            for (int mf = 0; mf < 2; mf++) {
                int row = wm * 32 + mf * 16 + aRow;
                int seg = 2 * t + aSegAdd;
                uint32_t off = row * 128 + (((seg ^ (row & 7)) << 4));
                ldsm4(ah[mf][0], ah[mf][1], ah[mf][2], ah[mf][3], sAh + off);
                ldsm4(al[mf][0], al[mf][1], al[mf][2], al[mf][3], sAl + off);
            }
#pragma unroll
            for (int p = 0; p < 4; p++) {
                int row = wn * 64 + p * 16 + bRowIn;
                int seg = 2 * t + bSegAdd;
                uint32_t off = row * 128 + (((seg ^ (row & 7)) << 4));
                ldsm4(bh[2 * p][0], bh[2 * p][1], bh[2 * p + 1][0], bh[2 * p + 1][1], sBh + off);
                ldsm4(bl[2 * p][0], bl[2 * p][1], bl[2 * p + 1][0], bl[2 * p + 1][1], sBl + off);
            }
#pragma unroll
            for (int mf = 0; mf < 2; mf++)
#pragma unroll
                for (int nb = 0; nb < 8; nb++) {
                    mma16816(acc[mf][nb], ah[mf], bh[nb]);
                    mma16816(acc[mf][nb], ah[mf], bl[nb]);
                    mma16816(acc[mf][nb], al[mf], bh[nb]);
                }
        }
        __syncthreads();
    }

    // epilogue: out = r[i]*acc + Xres
#pragma unroll
    for (int mf = 0; mf < 2; mf++) {
        int row0 = wm * 32 + mf * 16 + (lid >> 2);
        int i0 = iBase + row0, i1 = i0 + 8;
        float ri0 = __ldg(&r[i0]), ri1 = __ldg(&r[i1]);
#pragma unroll
        for (int nb = 0; nb < 8; nb++) {
            int col = nBase + wn * 64 + nb * 8 + (lid & 3) * 2;
            size_t o0 = (size_t)i0 * ncols + col;
            size_t o1 = (size_t)i1 * ncols + col;
            float2 s0 = *(const float2*)(Xres + o0);
            float2 s1 = *(const float2*)(Xres + o1);
            float2 v0 = make_float2(fmaf(ri0, acc[mf][nb][0], s0.x), fmaf(ri0, acc[mf][nb][1], s0.y));
            float2 v1 = make_float2(fmaf(ri1, acc[mf][nb][2], s1.x), fmaf(ri1, acc[mf][nb][3], s1.y));
            *(float2*)(Out + o0) = v0;
            *(float2*)(Out + o1) = v1;
        }
    }
}

// ---------------- K4: per node: (y @ W1 + b1) -> L2norm -> relu -> BN ----------------
__global__ __launch_bounds__(128)
void k_layer1(const float* __restrict__ Y, const float* __restrict__ W1,
              const float* __restrict__ b1, float* __restrict__ G) {
    __shared__ float W1s[DDIM * HDIM];
    __shared__ float Ys[BB * DDIM];
    __shared__ float red[128];
    int i = blockIdx.x, tid = threadIdx.x;
    for (int t = tid; t < DDIM * HDIM; t += 128) W1s[t] = W1[t];
    for (int t = tid; t < BB * DDIM; t += 128) Ys[t] = Y[(size_t)i * 256 + t];
    __syncthreads();

    float v[BB];
    float bias = b1[tid];
#pragma unroll
    for (int b = 0; b < BB; b++) v[b] = bias;
#pragma unroll 4
    for (int d = 0; d < DDIM; d++) {
        float w = W1s[d * HDIM + tid];
#pragma unroll
        for (int b = 0; b < BB; b++) v[b] = fmaf(Ys[b * DDIM + d], w, v[b]);
    }
#pragma unroll
    for (int b = 0; b < BB; b++) {
        float ss = block_sum<128>(v[b] * v[b], red, tid);
        float nrm = fmaxf(sqrtf(ss), 1e-12f);
        v[b] = fmaxf(v[b] / nrm, 0.f);
    }
    float s = v[0] + v[1] + v[2] + v[3];
    float mean = block_sum<128>(s, red, tid) * (1.f / 512.f);
    float q = 0.f;
#pragma unroll
    for (int b = 0; b < BB; b++) { float d = v[b] - mean; q = fmaf(d, d, q); }
    float var = block_sum<128>(q, red, tid) * (1.f / 512.f);
    float inv = rsqrtf(var + 1e-5f);
#pragma unroll
    for (int b = 0; b < BB; b++)
        G[(size_t)i * 512 + b * HDIM + tid] = (v[b] - mean) * inv;
}

// ---------------- K6: per node layer2 + project ----------------
__global__ __launch_bounds__(256)
void k_layer2(const float* __restrict__ Y, const float* __restrict__ W2,
              const float* __restrict__ b2, const float* __restrict__ Wp,
              const float* __restrict__ bp, float* __restrict__ PT) {
    __shared__ float Ys[BB * HDIM];
    __shared__ float red[256];
    __shared__ float gS[BB][EDIM];
    int i = blockIdx.x, tid = threadIdx.x;
    for (int t = tid; t < BB * HDIM; t += 256) Ys[t] = Y[(size_t)i * 512 + t];
    __syncthreads();

    float v[BB];
    float bias = b2[tid];
#pragma unroll
    for (int b = 0; b < BB; b++) v[b] = bias;
#pragma unroll 4
    for (int h = 0; h < HDIM; h++) {
        float w = __ldg(&W2[h * EDIM + tid]);
#pragma unroll
        for (int b = 0; b < BB; b++) v[b] = fmaf(Ys[b * HDIM + h], w, v[b]);
    }
#pragma unroll
    for (int b = 0; b < BB; b++) {
        float ss = block_sum<256>(v[b] * v[b], red, tid);
        float nrm = fmaxf(sqrtf(ss), 1e-12f);
        v[b] = fmaxf(v[b] / nrm, 0.f);
    }
    float s = v[0] + v[1] + v[2] + v[3];
    float mean = block_sum<256>(s, red, tid) * (1.f / 1024.f);
    float q = 0.f;
#pragma unroll
    for (int b = 0; b < BB; b++) { float d = v[b] - mean; q = fmaf(d, d, q); }
    float var = block_sum<256>(q, red, tid) * (1.f / 1024.f);
    float inv = rsqrtf(var + 1e-5f);
#pragma unroll
    for (int b = 0; b < BB; b++) gS[b][tid] = (v[b] - mean) * inv;
    __syncthreads();

    if (tid < BB * CDIM) {
        int b = tid >> 4, c = tid & 15;
        float acc = bp[c];
#pragma unroll 8
        for (int e = 0; e < EDIM; e++) acc = fmaf(gS[b][e], Wp[e * CDIM + c], acc);
        PT[(size_t)(b * CDIM + c) * NN + i] = acc;
    }
}

// ---------------- K7: softmax over nodes ----------------
__global__ __launch_bounds__(256)
void k_softmax(const float* __restrict__ PT, float* __restrict__ out) {
    __shared__ float row[NN];
    __shared__ float red[256];
    int bc = blockIdx.x, tid = threadIdx.x;
    int b = bc >> 4, c = bc & 15;
    const float* p = PT + (size_t)bc * NN;
    float mx = -3.4e38f;
    for (int t = tid; t < NN; t += 256) { float v = p[t]; row[t] = v; mx = fmaxf(mx, v); }
    mx = block_max<256>(mx, red, tid);
    float s = 0.f;
    for (int t = tid; t < NN; t += 256) { float e = expf(row[t] - mx); row[t] = e; s += e; }
    s = block_sum<256>(s, red, tid);
    float inv = 1.f / s;
    for (int t = tid; t < NN; t += 256)
        out[((size_t)b * NN + t) * CDIM + c] = row[t] * inv;
}

// ---------------- launch ----------------
extern "C" void kernel_launch(void* const* d_in, const int* in_sizes, int n_in,
                              void* d_out, int out_size) {
    const float* x   = (const float*)d_in[0];
    const float* adj = (const float*)d_in[1];
    const float* W1  = (const float*)d_in[2];
    const float* b1  = (const float*)d_in[3];
    const float* W2  = (const float*)d_in[4];
    const float* b2  = (const float*)d_in[5];
    const float* Wp  = (const float*)d_in[6];
    const float* bp  = (const float*)d_in[7];
    float* out = (float*)d_out;

    float *r_, *xt_, *y1_, *g1_, *y2_, *pt_;
    __nv_bfloat16 *ath_, *atl_, *xbh_, *xbl_, *g1h_, *g1l_;
    cudaGetSymbolAddress((void**)&r_,  g_r);
    cudaGetSymbolAddress((void**)&xt_, g_xt);
    cudaGetSymbolAddress((void**)&y1_, g_y1);
    cudaGetSymbolAddress((void**)&g1_, g_g1);
    cudaGetSymbolAddress((void**)&y2_, g_y2);
    cudaGetSymbolAddress((void**)&pt_, g_pt);
    cudaGetSymbolAddress((void**)&ath_, g_ath);
    cudaGetSymbolAddress((void**)&atl_, g_atl);
    cudaGetSymbolAddress((void**)&xbh_, g_xbh);
    cudaGetSymbolAddress((void**)&xbl_, g_xbl);
    cudaGetSymbolAddress((void**)&g1h_, g_g1h);
    cudaGetSymbolAddress((void**)&g1l_, g_g1l);

    static bool attr_set = false;
    if (!attr_set) {
        cudaFuncSetAttribute(k_gemm_mma, cudaFuncAttributeMaxDynamicSharedMemorySize, GSMEM);
        attr_set = true;
    }

    k_rowsum<<<NN, 256>>>(adj, r_);
    k_prep_x<<<dim3(NN / 32, 256 / 32), dim3(32, 8)>>>(x, xt_, xbh_, xbl_);
    k_prep_adj<<<dim3(NN / 32, NN / 32), dim3(32, 8)>>>(adj, r_, ath_, atl_);
    k_gemm_mma<<<dim3(2, NN / 128), 256, GSMEM>>>(ath_, atl_, xbh_, xbl_, r_, xt_, y1_, 256);
    k_layer1<<<NN, 128>>>(y1_, W1, b1, g1_);
    k_g1t<<<dim3(NN / 32, 512 / 32), dim3(32, 8)>>>(g1_, g1h_, g1l_);
    k_gemm_mma<<<dim3(4, NN / 128), 256, GSMEM>>>(ath_, atl_, g1h_, g1l_, r_, g1_, y2_, 512);
    k_layer2<<<NN, 256>>>(y2_, W2, b2, Wp, bp, pt_);
    k_softmax<<<BB * CDIM, 256>>>(pt_, out);
}